// round 1
// baseline (speedup 1.0000x reference)
#include <cuda_runtime.h>
#include <math.h>
#include <stdint.h>

static constexpr int SEQ    = 2048;
static constexpr int DMODEL = 768;
static constexpr int NHEAD  = 12;
static constexpr int HDIM   = 64;

// ---------------------------------------------------------------------------
// Scratch (no allocations allowed -> __device__ globals)
// ---------------------------------------------------------------------------
__device__ float g_q [SEQ * DMODEL];            // x @ Wq^T   (fp32)
__device__ float g_k [SEQ * DMODEL];            // x @ Wk^T
__device__ float g_v [SEQ * DMODEL];            // x @ Wv^T
__device__ float g_qb[NHEAD * SEQ * HDIM];      // normed+rope+scaled Q, [h][t][d], tf32-rounded
__device__ float g_kb[NHEAD * SEQ * HDIM];      // normed+rope K, [h][t][d], tf32-rounded
__device__ float g_vt[NHEAD * HDIM * SEQ];      // blended V transposed, [h][d][t], tf32-rounded
__device__ float g_ob[SEQ * DMODEL];            // attention output, [t][h*64+d] (fp32)

// ---------------------------------------------------------------------------
// Helpers
// ---------------------------------------------------------------------------
__device__ __forceinline__ float to_tf32(float x) {
    uint32_t u;
    asm("cvt.rna.tf32.f32 %0, %1;" : "=r"(u) : "f"(x));
    return __uint_as_float(u);
}

// D += A * B : m16n8k8 tf32 mma. a: 4 regs, b: 2 regs, d: 4 f32.
__device__ __forceinline__ void mma8(float* d, const float* a, const float* b) {
    asm volatile(
        "mma.sync.aligned.m16n8k8.row.col.f32.tf32.tf32.f32 "
        "{%0,%1,%2,%3}, {%4,%5,%6,%7}, {%8,%9}, {%0,%1,%2,%3};\n"
        : "+f"(d[0]), "+f"(d[1]), "+f"(d[2]), "+f"(d[3])
        : "r"(__float_as_uint(a[0])), "r"(__float_as_uint(a[1])),
          "r"(__float_as_uint(a[2])), "r"(__float_as_uint(a[3])),
          "r"(__float_as_uint(b[0])), "r"(__float_as_uint(b[1])));
}

__device__ __forceinline__ float red_max4(float v) {
    v = fmaxf(v, __shfl_xor_sync(0xffffffffu, v, 1));
    v = fmaxf(v, __shfl_xor_sync(0xffffffffu, v, 2));
    return v;
}
__device__ __forceinline__ float red_sum4(float v) {
    v += __shfl_xor_sync(0xffffffffu, v, 1);
    v += __shfl_xor_sync(0xffffffffu, v, 2);
    return v;
}

// ---------------------------------------------------------------------------
// GEMM core: C[128 x 128] tile of  A[*,768] @ B[*,768]^T  (both K-major rows),
// K = 768, tf32 mma, register-staged global prefetch.
// 256 threads = 8 warps (2 M-warps x 4 N-warps); warp tile 64x32.
// ---------------------------------------------------------------------------
__device__ __forceinline__ void gemm_core(const float* __restrict__ At,
                                          const float* __restrict__ Bt,
                                          float* __restrict__ Ct, int ldc)
{
    __shared__ float As[128][36];
    __shared__ float Bs[128][36];

    const int tid  = threadIdx.x;
    const int warp = tid >> 5, lane = tid & 31;
    const int wm = warp & 1, wn = warp >> 1;
    const int g  = lane >> 2, t4 = lane & 3;

    float acc[4][4][4];
#pragma unroll
    for (int i = 0; i < 4; i++)
#pragma unroll
        for (int j = 0; j < 4; j++)
#pragma unroll
            for (int e = 0; e < 4; e++) acc[i][j][e] = 0.f;

    float4 ra[4], rb[4];

    // prefetch kt = 0
#pragma unroll
    for (int v = 0; v < 4; v++) {
        int idx = tid + v * 256;
        int r = idx >> 3, c4 = idx & 7;
        ra[v] = *(const float4*)(At + r * DMODEL + c4 * 4);
        rb[v] = *(const float4*)(Bt + r * DMODEL + c4 * 4);
    }
#pragma unroll
    for (int v = 0; v < 4; v++) {
        int idx = tid + v * 256;
        int r = idx >> 3, c4 = idx & 7;
        float4 a = ra[v], b = rb[v];
        As[r][c4*4+0] = to_tf32(a.x); As[r][c4*4+1] = to_tf32(a.y);
        As[r][c4*4+2] = to_tf32(a.z); As[r][c4*4+3] = to_tf32(a.w);
        Bs[r][c4*4+0] = to_tf32(b.x); Bs[r][c4*4+1] = to_tf32(b.y);
        Bs[r][c4*4+2] = to_tf32(b.z); Bs[r][c4*4+3] = to_tf32(b.w);
    }
    __syncthreads();

    const int NKT = DMODEL / 32;  // 24
    for (int kt = 0; kt < NKT; kt++) {
        if (kt + 1 < NKT) {
#pragma unroll
            for (int v = 0; v < 4; v++) {
                int idx = tid + v * 256;
                int r = idx >> 3, c4 = idx & 7;
                ra[v] = *(const float4*)(At + r * DMODEL + (kt + 1) * 32 + c4 * 4);
                rb[v] = *(const float4*)(Bt + r * DMODEL + (kt + 1) * 32 + c4 * 4);
            }
        }
#pragma unroll
        for (int kk = 0; kk < 4; kk++) {
            float af[4][4], bf[4][2];
#pragma unroll
            for (int mt = 0; mt < 4; mt++) {
                int r = wm * 64 + mt * 16 + g;
                af[mt][0] = As[r    ][kk * 8 + t4];
                af[mt][1] = As[r + 8][kk * 8 + t4];
                af[mt][2] = As[r    ][kk * 8 + t4 + 4];
                af[mt][3] = As[r + 8][kk * 8 + t4 + 4];
            }
#pragma unroll
            for (int nt = 0; nt < 4; nt++) {
                int c = wn * 32 + nt * 8 + g;
                bf[nt][0] = Bs[c][kk * 8 + t4];
                bf[nt][1] = Bs[c][kk * 8 + t4 + 4];
            }
#pragma unroll
            for (int mt = 0; mt < 4; mt++)
#pragma unroll
                for (int nt = 0; nt < 4; nt++)
                    mma8(acc[mt][nt], af[mt], bf[nt]);
        }
        __syncthreads();
        if (kt + 1 < NKT) {
#pragma unroll
            for (int v = 0; v < 4; v++) {
                int idx = tid + v * 256;
                int r = idx >> 3, c4 = idx & 7;
                float4 a = ra[v], b = rb[v];
                As[r][c4*4+0] = to_tf32(a.x); As[r][c4*4+1] = to_tf32(a.y);
                As[r][c4*4+2] = to_tf32(a.z); As[r][c4*4+3] = to_tf32(a.w);
                Bs[r][c4*4+0] = to_tf32(b.x); Bs[r][c4*4+1] = to_tf32(b.y);
                Bs[r][c4*4+2] = to_tf32(b.z); Bs[r][c4*4+3] = to_tf32(b.w);
            }
            __syncthreads();
        }
    }

#pragma unroll
    for (int mt = 0; mt < 4; mt++) {
        int r0 = wm * 64 + mt * 16 + g;
#pragma unroll
        for (int nt = 0; nt < 4; nt++) {
            int c0 = wn * 32 + nt * 8 + 2 * t4;
            *(float2*)(Ct + r0 * ldc + c0)       = make_float2(acc[mt][nt][0], acc[mt][nt][1]);
            *(float2*)(Ct + (r0 + 8) * ldc + c0) = make_float2(acc[mt][nt][2], acc[mt][nt][3]);
        }
    }
}

// ---------------------------------------------------------------------------
// Kernel 1: fused QKV projection.  grid (16, 18)
// ---------------------------------------------------------------------------
__global__ void __launch_bounds__(256)
gemm_qkv_kernel(const float* __restrict__ x,
                const float* __restrict__ wq,
                const float* __restrict__ wk,
                const float* __restrict__ wv)
{
    int bm = blockIdx.x;
    int nb = blockIdx.y;            // 0..17
    int sel = nb / 6, bn = nb % 6;
    const float* B = (sel == 0) ? wq : (sel == 1) ? wk : wv;
    float* C       = (sel == 0) ? g_q : (sel == 1) ? g_k : g_v;
    gemm_core(x + bm * 128 * DMODEL, B + bn * 128 * DMODEL,
              C + bm * 128 * DMODEL + bn * 128, DMODEL);
}

// ---------------------------------------------------------------------------
// Kernel 2: V blend + RMS-norm(q,k) + RoPE + layout shuffles.  grid (12, 64)
// One warp per (t, h) sub-row; lane i owns elems i and i+32 (the RoPE pair).
// ---------------------------------------------------------------------------
__global__ void __launch_bounds__(256)
epilogue_kernel(const float* __restrict__ vi, const float* __restrict__ lambp)
{
    const int h  = blockIdx.x;
    const int t0 = blockIdx.y * 32;
    const int tid = threadIdx.x, warp = tid >> 5, lane = tid & 31;
    const float lamb = *lambp;

    __shared__ float vsh[64][33];

    // RoPE frequency for this lane (pairs (i, i+32)); matches jax fp32 math.
    const float invf = powf(1e-4f, (float)lane * (1.0f / 32.0f));

#pragma unroll
    for (int it = 0; it < 4; it++) {
        const int tl = warp * 4 + it;        // 0..31
        const int t  = t0 + tl;
        const int base = t * DMODEL + h * 64 + lane;

        float q1 = g_q[base], q2 = g_q[base + 32];
        float k1 = g_k[base], k2 = g_k[base + 32];
        float v1 = g_v[base], v2 = g_v[base + 32];
        float w1 = vi[base],  w2 = vi[base + 32];
        v1 = (1.f - lamb) * v1 + lamb * w1;
        v2 = (1.f - lamb) * v2 + lamb * w2;

        // RMS norm (eps = float32 machine epsilon, matching jnp.finfo)
        float sq = q1 * q1 + q2 * q2;
        float sk = k1 * k1 + k2 * k2;
#pragma unroll
        for (int m = 16; m; m >>= 1) {
            sq += __shfl_xor_sync(0xffffffffu, sq, m);
            sk += __shfl_xor_sync(0xffffffffu, sk, m);
        }
        const float rq = rsqrtf(sq * (1.f / 64.f) + 1.1920929e-7f);
        const float rk = rsqrtf(sk * (1.f / 64.f) + 1.1920929e-7f);
        q1 *= rq; q2 *= rq; k1 *= rk; k2 *= rk;

        // RoPE
        const float ang = (float)t * invf;
        float s, c;
        sincosf(ang, &s, &c);
        float qa =  q1 * c + q2 * s;
        float qb = -q1 * s + q2 * c;
        float ka =  k1 * c + k2 * s;
        float kb = -k1 * s + k2 * c;

        // fold attention scale 1/sqrt(64) into q
        qa *= 0.125f; qb *= 0.125f;

        const int ob = (h * SEQ + t) * 64 + lane;
        g_qb[ob]      = to_tf32(qa);
        g_qb[ob + 32] = to_tf32(qb);
        g_kb[ob]      = to_tf32(ka);
        g_kb[ob + 32] = to_tf32(kb);

        vsh[lane][tl]      = to_tf32(v1);
        vsh[lane + 32][tl] = to_tf32(v2);
    }
    __syncthreads();

    // write V transposed [h][d][t], coalesced
#pragma unroll
    for (int v = 0; v < 8; v++) {
        int idx = tid + v * 256;         // 0..2047
        int d = idx >> 5, tl = idx & 31;
        g_vt[(h * 64 + d) * SEQ + t0 + tl] = vsh[d][tl];
    }
}

// ---------------------------------------------------------------------------
// Kernel 3: causal flash attention.  grid (32, 12), 128 threads (4 warps).
// Each CTA: 64 queries of one head. KV tiles of 64. tf32 mma for S and P@V.
// ---------------------------------------------------------------------------
__global__ void __launch_bounds__(128)
attn_kernel()
{
    extern __shared__ float sm_attn[];
    float (*qs)[68] = (float(*)[68])(sm_attn);
    float (*ks)[68] = (float(*)[68])(sm_attn + 64 * 68);
    float (*vs)[68] = (float(*)[68])(sm_attn + 2 * 64 * 68);
    float (*ps)[68] = (float(*)[68])(sm_attn + 3 * 64 * 68);

    const int qt = blockIdx.x;          // q tile 0..31
    const int h  = blockIdx.y;
    const int tid = threadIdx.x, w = tid >> 5, lane = tid & 31;
    const int g = lane >> 2, t4 = lane & 3;

    // load Q tile (already normed/roped/scaled/tf32)
    const float* qg = g_qb + (h * SEQ + qt * 64) * 64;
#pragma unroll
    for (int v = 0; v < 8; v++) {
        int idx = tid + v * 128;
        int r = idx >> 4, c4 = idx & 15;
        *(float4*)&qs[r][c4 * 4] = *(const float4*)(qg + r * 64 + c4 * 4);
    }

    float o[8][4];
#pragma unroll
    for (int nt = 0; nt < 8; nt++)
#pragma unroll
        for (int e = 0; e < 4; e++) o[nt][e] = 0.f;
    float m0 = -INFINITY, m1 = -INFINITY, l0 = 0.f, l1 = 0.f;

    for (int jt = 0; jt <= qt; jt++) {
        // load K tile and V^T tile
        const float* kg = g_kb + (h * SEQ + jt * 64) * 64;
        const float* vg = g_vt + (h * 64) * SEQ + jt * 64;
#pragma unroll
        for (int v = 0; v < 8; v++) {
            int idx = tid + v * 128;
            int r = idx >> 4, c4 = idx & 15;
            *(float4*)&ks[r][c4 * 4] = *(const float4*)(kg + r * 64 + c4 * 4);
            *(float4*)&vs[r][c4 * 4] = *(const float4*)(vg + r * SEQ + c4 * 4);
        }
        __syncthreads();

        // S = Q K^T  (warp rows [w*16, w*16+16))
        float s[8][4];
#pragma unroll
        for (int nt = 0; nt < 8; nt++)
#pragma unroll
            for (int e = 0; e < 4; e++) s[nt][e] = 0.f;
#pragma unroll
        for (int kk = 0; kk < 8; kk++) {
            float af[4];
            int r = w * 16 + g;
            af[0] = qs[r    ][kk * 8 + t4];
            af[1] = qs[r + 8][kk * 8 + t4];
            af[2] = qs[r    ][kk * 8 + t4 + 4];
            af[3] = qs[r + 8][kk * 8 + t4 + 4];
#pragma unroll
            for (int nt = 0; nt < 8; nt++) {
                float bf[2];
                bf[0] = ks[nt * 8 + g][kk * 8 + t4];
                bf[1] = ks[nt * 8 + g][kk * 8 + t4 + 4];
                mma8(s[nt], af, bf);
            }
        }

        // causal mask (only diagonal tile)
        if (jt == qt) {
            const int r0 = w * 16 + g;
#pragma unroll
            for (int nt = 0; nt < 8; nt++) {
                int c0 = nt * 8 + 2 * t4;
                if (c0     > r0    ) s[nt][0] = -1e30f;
                if (c0 + 1 > r0    ) s[nt][1] = -1e30f;
                if (c0     > r0 + 8) s[nt][2] = -1e30f;
                if (c0 + 1 > r0 + 8) s[nt][3] = -1e30f;
            }
        }

        // online softmax
        float mx0 = -INFINITY, mx1 = -INFINITY;
#pragma unroll
        for (int nt = 0; nt < 8; nt++) {
            mx0 = fmaxf(mx0, fmaxf(s[nt][0], s[nt][1]));
            mx1 = fmaxf(mx1, fmaxf(s[nt][2], s[nt][3]));
        }
        mx0 = red_max4(mx0);
        mx1 = red_max4(mx1);
        const float mn0 = fmaxf(m0, mx0), mn1 = fmaxf(m1, mx1);
        const float a0 = __expf(m0 - mn0), a1 = __expf(m1 - mn1);

        float rs0 = 0.f, rs1 = 0.f;
#pragma unroll
        for (int nt = 0; nt < 8; nt++) {
            s[nt][0] = __expf(s[nt][0] - mn0);
            s[nt][1] = __expf(s[nt][1] - mn0);
            s[nt][2] = __expf(s[nt][2] - mn1);
            s[nt][3] = __expf(s[nt][3] - mn1);
            rs0 += s[nt][0] + s[nt][1];
            rs1 += s[nt][2] + s[nt][3];
        }
        rs0 = red_sum4(rs0);
        rs1 = red_sum4(rs1);
        l0 = l0 * a0 + rs0;
        l1 = l1 * a1 + rs1;
#pragma unroll
        for (int nt = 0; nt < 8; nt++) {
            o[nt][0] *= a0; o[nt][1] *= a0;
            o[nt][2] *= a1; o[nt][3] *= a1;
        }
        m0 = mn0; m1 = mn1;

        // write P (tf32-rounded) to shared for the PV mma
        {
            const int r0 = w * 16 + g;
#pragma unroll
            for (int nt = 0; nt < 8; nt++) {
                int c0 = nt * 8 + 2 * t4;
                ps[r0    ][c0]     = to_tf32(s[nt][0]);
                ps[r0    ][c0 + 1] = to_tf32(s[nt][1]);
                ps[r0 + 8][c0]     = to_tf32(s[nt][2]);
                ps[r0 + 8][c0 + 1] = to_tf32(s[nt][3]);
            }
        }
        __syncthreads();

        // O += P @ V   (B = V^T from vs[d][kp])
#pragma unroll
        for (int kk = 0; kk < 8; kk++) {
            float af[4];
            int r = w * 16 + g;
            af[0] = ps[r    ][kk * 8 + t4];
            af[1] = ps[r + 8][kk * 8 + t4];
            af[2] = ps[r    ][kk * 8 + t4 + 4];
            af[3] = ps[r + 8][kk * 8 + t4 + 4];
#pragma unroll
            for (int nt = 0; nt < 8; nt++) {
                float bf[2];
                bf[0] = vs[nt * 8 + g][kk * 8 + t4];
                bf[1] = vs[nt * 8 + g][kk * 8 + t4 + 4];
                mma8(o[nt], af, bf);
            }
        }
        __syncthreads();
    }

    // normalize and write [t][h*64+d]
    const float il0 = 1.f / l0, il1 = 1.f / l1;
    const int tr0 = qt * 64 + w * 16 + g;
#pragma unroll
    for (int nt = 0; nt < 8; nt++) {
        int col = h * 64 + nt * 8 + 2 * t4;
        *(float2*)(g_ob + tr0 * DMODEL + col) =
            make_float2(o[nt][0] * il0, o[nt][1] * il0);
        *(float2*)(g_ob + (tr0 + 8) * DMODEL + col) =
            make_float2(o[nt][2] * il1, o[nt][3] * il1);
    }
}

// ---------------------------------------------------------------------------
// Kernel 4: output projection.  grid (16, 6)
// ---------------------------------------------------------------------------
__global__ void __launch_bounds__(256)
gemm_proj_kernel(const float* __restrict__ wp, float* __restrict__ out)
{
    int bm = blockIdx.x, bn = blockIdx.y;
    gemm_core(g_ob + bm * 128 * DMODEL, wp + bn * 128 * DMODEL,
              out + bm * 128 * DMODEL + bn * 128, DMODEL);
}

// ---------------------------------------------------------------------------
// Launch
// ---------------------------------------------------------------------------
extern "C" void kernel_launch(void* const* d_in, const int* in_sizes, int n_in,
                              void* d_out, int out_size)
{
    (void)in_sizes; (void)n_in; (void)out_size;
    const float* x    = (const float*)d_in[0];
    const float* vi   = (const float*)d_in[1];
    const float* Wq   = (const float*)d_in[2];
    const float* Wk   = (const float*)d_in[3];
    const float* Wv   = (const float*)d_in[4];
    const float* Wp   = (const float*)d_in[5];
    const float* lamb = (const float*)d_in[6];

    gemm_qkv_kernel<<<dim3(16, 18), 256>>>(x, Wq, Wk, Wv);
    epilogue_kernel<<<dim3(12, 64), 256>>>(vi, lamb);

    const int attn_smem = 4 * 64 * 68 * (int)sizeof(float);  // 69632 B
    cudaFuncSetAttribute(attn_kernel, cudaFuncAttributeMaxDynamicSharedMemorySize,
                         attn_smem);
    attn_kernel<<<dim3(32, 12), 128, attn_smem>>>();

    gemm_proj_kernel<<<dim3(16, 6), 256>>>(Wp, (float*)d_out);
}

// round 3
// speedup vs baseline: 1.0448x; 1.0448x over previous
#include <cuda_runtime.h>
#include <math.h>
#include <stdint.h>

static constexpr int SEQ    = 2048;
static constexpr int DMODEL = 768;
static constexpr int NHEAD  = 12;
static constexpr int HDIM   = 64;

// ---------------------------------------------------------------------------
// Scratch (no allocations allowed -> __device__ globals)
// ---------------------------------------------------------------------------
__device__ float g_xr [SEQ * DMODEL];           // tf32-rounded x
__device__ float g_wr [3 * DMODEL * DMODEL];    // tf32-rounded [Wq;Wk;Wv]
__device__ float g_wpr[DMODEL * DMODEL];        // tf32-rounded Wp
__device__ float g_q [SEQ * DMODEL];            // x @ Wq^T   (fp32)
__device__ float g_k [SEQ * DMODEL];            // x @ Wk^T
__device__ float g_v [SEQ * DMODEL];            // x @ Wv^T
__device__ float g_qb[NHEAD * SEQ * HDIM];      // normed+rope+scaled Q, [h][t][d], tf32
__device__ float g_kb[NHEAD * SEQ * HDIM];      // normed+rope K, [h][t][d], tf32
__device__ float g_vt[NHEAD * HDIM * SEQ];      // blended V transposed, [h][d][t], tf32
__device__ float g_ob[SEQ * DMODEL];            // attention output, [t][h*64+d], tf32

// ---------------------------------------------------------------------------
// Helpers
// ---------------------------------------------------------------------------
__device__ __forceinline__ float to_tf32(float x) {
    uint32_t u;
    asm("cvt.rna.tf32.f32 %0, %1;" : "=r"(u) : "f"(x));
    return __uint_as_float(u);
}

__device__ __forceinline__ uint32_t smem_u32(const void* p) {
    uint32_t a;
    asm("{ .reg .u64 t; cvta.to.shared.u64 t, %1; cvt.u32.u64 %0, t; }"
        : "=r"(a) : "l"(p));
    return a;
}

__device__ __forceinline__ void cp_async16(uint32_t s, const void* g) {
    asm volatile("cp.async.cg.shared.global [%0], [%1], 16;" :: "r"(s), "l"(g));
}
__device__ __forceinline__ void cp_commit() {
    asm volatile("cp.async.commit_group;" ::: "memory");
}
template <int N>
__device__ __forceinline__ void cp_wait() {
    asm volatile("cp.async.wait_group %0;" :: "n"(N) : "memory");
}

// D += A * B : m16n8k8 tf32 mma. a: 4 regs, b: 2 regs, d: 4 f32.
__device__ __forceinline__ void mma8(float* d, const float* a, const float* b) {
    asm volatile(
        "mma.sync.aligned.m16n8k8.row.col.f32.tf32.tf32.f32 "
        "{%0,%1,%2,%3}, {%4,%5,%6,%7}, {%8,%9}, {%0,%1,%2,%3};\n"
        : "+f"(d[0]), "+f"(d[1]), "+f"(d[2]), "+f"(d[3])
        : "r"(__float_as_uint(a[0])), "r"(__float_as_uint(a[1])),
          "r"(__float_as_uint(a[2])), "r"(__float_as_uint(a[3])),
          "r"(__float_as_uint(b[0])), "r"(__float_as_uint(b[1])));
}

__device__ __forceinline__ float red_max4(float v) {
    v = fmaxf(v, __shfl_xor_sync(0xffffffffu, v, 1));
    v = fmaxf(v, __shfl_xor_sync(0xffffffffu, v, 2));
    return v;
}
__device__ __forceinline__ float red_sum4(float v) {
    v += __shfl_xor_sync(0xffffffffu, v, 1);
    v += __shfl_xor_sync(0xffffffffu, v, 2);
    return v;
}

// ---------------------------------------------------------------------------
// Kernel 0: rna-tf32 pre-round of x and all weights (one float4 per thread)
// ---------------------------------------------------------------------------
__global__ void __launch_bounds__(256)
round_kernel(const float* __restrict__ x,  const float* __restrict__ wq,
             const float* __restrict__ wk, const float* __restrict__ wv,
             const float* __restrict__ wp)
{
    int i = blockIdx.x * 256 + threadIdx.x;  // float4 index, total 983040
    const float* src;
    float* dst;
    int off;
    if (i < 393216)       { src = x;  dst = g_xr;           off = i; }
    else if (i < 540672)  { src = wq; dst = g_wr;           off = i - 393216; }
    else if (i < 688128)  { src = wk; dst = g_wr + 589824;  off = i - 540672; }
    else if (i < 835584)  { src = wv; dst = g_wr + 1179648; off = i - 688128; }
    else                  { src = wp; dst = g_wpr;          off = i - 835584; }
    float4 v = ((const float4*)src)[off];
    v.x = to_tf32(v.x); v.y = to_tf32(v.y);
    v.z = to_tf32(v.z); v.w = to_tf32(v.w);
    ((float4*)dst)[off] = v;
}

// ---------------------------------------------------------------------------
// Templated tf32 mma.sync GEMM core: C[BM x BN] tile of A[*,768] @ B[*,768]^T.
// A, B pre-rounded to tf32.  256 threads = 8 warps, warp grid WGM x WGN.
// K chunks of 32 floats, cp.async double-buffered (stride 36 floats = 144 B,
// conflict-free fragment LDS).
// Dynamic smem: A bufs [2][BM][36], then B bufs [2][BN][36].
// ---------------------------------------------------------------------------
template <int BM, int BN, int WGM, int WGN>
__device__ __forceinline__ void gemm_mma_core(const float* __restrict__ A,
                                              const float* __restrict__ B,
                                              float* __restrict__ C, int ldc)
{
    constexpr int MT = BM / WGM / 16;       // m16 blocks per warp
    constexpr int NT = BN / WGN / 8;        // n8 blocks per warp
    constexpr int NKT = DMODEL / 32;        // 24
    constexpr int ACH = BM / 32;            // A 16B-chunks per thread
    constexpr int BCH = BN / 32;            // B 16B-chunks per thread

    extern __shared__ float sm[];
    const uint32_t sb = smem_u32(sm);
    const uint32_t aOff[2] = {0u, (uint32_t)(BM * 36 * 4)};
    const uint32_t bBase   = (uint32_t)(2 * BM * 36 * 4);
    const uint32_t bOff[2] = {bBase, bBase + (uint32_t)(BN * 36 * 4)};

    const int tid  = threadIdx.x;
    const int warp = tid >> 5, lane = tid & 31;
    const int wm = warp % WGM, wn = warp / WGM;
    const int g  = lane >> 2, t4 = lane & 3;

    float acc[MT][NT][4];
#pragma unroll
    for (int i = 0; i < MT; i++)
#pragma unroll
        for (int j = 0; j < NT; j++)
#pragma unroll
            for (int e = 0; e < 4; e++) acc[i][j][e] = 0.f;

    auto issue = [&](int buf, int kt) {
        const float* ga = A + kt * 32;
#pragma unroll
        for (int v = 0; v < ACH; v++) {
            int idx = tid + v * 256, r = idx >> 3, c4 = idx & 7;
            cp_async16(sb + aOff[buf] + (uint32_t)(r * 144 + c4 * 16),
                       ga + r * DMODEL + c4 * 4);
        }
        const float* gb = B + kt * 32;
#pragma unroll
        for (int v = 0; v < BCH; v++) {
            int idx = tid + v * 256, r = idx >> 3, c4 = idx & 7;
            cp_async16(sb + bOff[buf] + (uint32_t)(r * 144 + c4 * 16),
                       gb + r * DMODEL + c4 * 4);
        }
        cp_commit();
    };

    issue(0, 0);

    for (int kt = 0; kt < NKT; kt++) {
        const int buf = kt & 1;
        if (kt + 1 < NKT) {
            issue(buf ^ 1, kt + 1);
            cp_wait<1>();
        } else {
            cp_wait<0>();
        }
        __syncthreads();

        const float (*As)[36] = (const float(*)[36])(sm + buf * BM * 36);
        const float (*Bs)[36] = (const float(*)[36])(sm + 2 * BM * 36 + buf * BN * 36);

#pragma unroll
        for (int kk = 0; kk < 4; kk++) {
            float af[MT][4], bf[NT][2];
#pragma unroll
            for (int mt = 0; mt < MT; mt++) {
                int r = wm * (BM / WGM) + mt * 16 + g;
                af[mt][0] = As[r    ][kk * 8 + t4];
                af[mt][1] = As[r + 8][kk * 8 + t4];
                af[mt][2] = As[r    ][kk * 8 + t4 + 4];
                af[mt][3] = As[r + 8][kk * 8 + t4 + 4];
            }
#pragma unroll
            for (int nt = 0; nt < NT; nt++) {
                int c = wn * (BN / WGN) + nt * 8 + g;
                bf[nt][0] = Bs[c][kk * 8 + t4];
                bf[nt][1] = Bs[c][kk * 8 + t4 + 4];
            }
#pragma unroll
            for (int mt = 0; mt < MT; mt++)
#pragma unroll
                for (int nt = 0; nt < NT; nt++)
                    mma8(acc[mt][nt], af[mt], bf[nt]);
        }
        __syncthreads();
    }

#pragma unroll
    for (int mt = 0; mt < MT; mt++) {
        int r0 = wm * (BM / WGM) + mt * 16 + g;
#pragma unroll
        for (int nt = 0; nt < NT; nt++) {
            int c0 = wn * (BN / WGN) + nt * 8 + 2 * t4;
            *(float2*)(C + r0 * ldc + c0)       = make_float2(acc[mt][nt][0], acc[mt][nt][1]);
            *(float2*)(C + (r0 + 8) * ldc + c0) = make_float2(acc[mt][nt][2], acc[mt][nt][3]);
        }
    }
}

static constexpr int QKV_SMEM  = 2 * (128 + 128) * 36 * 4;  // 73728
static constexpr int PROJ_SMEM = 2 * (128 +  64) * 36 * 4;  // 55296

// Kernel 1: fused QKV projection. grid (16, 18): 288 CTAs, all resident @occ2
__global__ void __launch_bounds__(256, 2)
gemm_qkv_k()
{
    int bm = blockIdx.x;
    int nb = blockIdx.y;                       // 0..17
    int sel = nb / 6, bn = nb % 6;
    float* Cbase = (sel == 0) ? g_q : (sel == 1) ? g_k : g_v;
    gemm_mma_core<128, 128, 2, 4>(g_xr + bm * 128 * DMODEL,
                                  g_wr + nb * 128 * DMODEL,
                                  Cbase + bm * 128 * DMODEL + bn * 128, DMODEL);
}

// Kernel 4: output projection. grid (16, 12): 192 CTAs (covers all SMs)
__global__ void __launch_bounds__(256, 2)
gemm_proj_k(float* __restrict__ out)
{
    gemm_mma_core<128, 64, 4, 2>(g_ob + blockIdx.x * 128 * DMODEL,
                                 g_wpr + blockIdx.y * 64 * DMODEL,
                                 out + blockIdx.x * 128 * DMODEL + blockIdx.y * 64,
                                 DMODEL);
}

// ---------------------------------------------------------------------------
// Kernel 2: V blend + RMS-norm(q,k) + RoPE + layout shuffles.  grid (12, 64)
// ---------------------------------------------------------------------------
__global__ void __launch_bounds__(256)
epilogue_kernel(const float* __restrict__ vi, const float* __restrict__ lambp)
{
    const int h  = blockIdx.x;
    const int t0 = blockIdx.y * 32;
    const int tid = threadIdx.x, warp = tid >> 5, lane = tid & 31;
    const float lamb = *lambp;

    __shared__ float vsh[64][33];

    const float invf = powf(1e-4f, (float)lane * (1.0f / 32.0f));

#pragma unroll
    for (int it = 0; it < 4; it++) {
        const int tl = warp * 4 + it;
        const int t  = t0 + tl;
        const int base = t * DMODEL + h * 64 + lane;

        float q1 = g_q[base], q2 = g_q[base + 32];
        float k1 = g_k[base], k2 = g_k[base + 32];
        float v1 = g_v[base], v2 = g_v[base + 32];
        float w1 = vi[base],  w2 = vi[base + 32];
        v1 = (1.f - lamb) * v1 + lamb * w1;
        v2 = (1.f - lamb) * v2 + lamb * w2;

        float sq = q1 * q1 + q2 * q2;
        float sk = k1 * k1 + k2 * k2;
#pragma unroll
        for (int m = 16; m; m >>= 1) {
            sq += __shfl_xor_sync(0xffffffffu, sq, m);
            sk += __shfl_xor_sync(0xffffffffu, sk, m);
        }
        const float rq = rsqrtf(sq * (1.f / 64.f) + 1.1920929e-7f);
        const float rk = rsqrtf(sk * (1.f / 64.f) + 1.1920929e-7f);
        q1 *= rq; q2 *= rq; k1 *= rk; k2 *= rk;

        const float ang = (float)t * invf;
        float s, c;
        sincosf(ang, &s, &c);
        float qa =  q1 * c + q2 * s;
        float qb = -q1 * s + q2 * c;
        float ka =  k1 * c + k2 * s;
        float kb = -k1 * s + k2 * c;

        qa *= 0.125f; qb *= 0.125f;

        const int ob = (h * SEQ + t) * 64 + lane;
        g_qb[ob]      = to_tf32(qa);
        g_qb[ob + 32] = to_tf32(qb);
        g_kb[ob]      = to_tf32(ka);
        g_kb[ob + 32] = to_tf32(kb);

        vsh[lane][tl]      = to_tf32(v1);
        vsh[lane + 32][tl] = to_tf32(v2);
    }
    __syncthreads();

#pragma unroll
    for (int v = 0; v < 8; v++) {
        int idx = tid + v * 256;
        int d = idx >> 5, tl = idx & 31;
        g_vt[(h * 64 + d) * SEQ + t0 + tl] = vsh[d][tl];
    }
}

// ---------------------------------------------------------------------------
// Kernel 3: causal flash attention.  grid (32, 12), 128 threads (4 warps).
// K/V tile loads via cp.async; P round-trip is intra-warp -> __syncwarp.
// ---------------------------------------------------------------------------
__global__ void __launch_bounds__(128)
attn_kernel()
{
    extern __shared__ float sm_attn[];
    float (*qs)[68] = (float(*)[68])(sm_attn);
    float (*ks)[68] = (float(*)[68])(sm_attn + 64 * 68);
    float (*vs)[68] = (float(*)[68])(sm_attn + 2 * 64 * 68);
    float (*ps)[68] = (float(*)[68])(sm_attn + 3 * 64 * 68);
    const uint32_t ksb = smem_u32(&ks[0][0]);
    const uint32_t vsb = smem_u32(&vs[0][0]);

    const int qt = blockIdx.x;
    const int h  = blockIdx.y;
    const int tid = threadIdx.x, w = tid >> 5, lane = tid & 31;
    const int g = lane >> 2, t4 = lane & 3;

    const float* qg = g_qb + (h * SEQ + qt * 64) * 64;
#pragma unroll
    for (int v = 0; v < 8; v++) {
        int idx = tid + v * 128;
        int r = idx >> 4, c4 = idx & 15;
        *(float4*)&qs[r][c4 * 4] = *(const float4*)(qg + r * 64 + c4 * 4);
    }

    float o[8][4];
#pragma unroll
    for (int nt = 0; nt < 8; nt++)
#pragma unroll
        for (int e = 0; e < 4; e++) o[nt][e] = 0.f;
    float m0 = -INFINITY, m1 = -INFINITY, l0 = 0.f, l1 = 0.f;

    for (int jt = 0; jt <= qt; jt++) {
        const float* kg = g_kb + (h * SEQ + jt * 64) * 64;
        const float* vg = g_vt + (h * 64) * SEQ + jt * 64;
#pragma unroll
        for (int v = 0; v < 8; v++) {
            int idx = tid + v * 128;
            int r = idx >> 4, c4 = idx & 15;
            cp_async16(ksb + (uint32_t)(r * 272 + c4 * 16), kg + r * 64 + c4 * 4);
            cp_async16(vsb + (uint32_t)(r * 272 + c4 * 16), vg + r * SEQ + c4 * 4);
        }
        cp_commit();
        cp_wait<0>();
        __syncthreads();

        float s[8][4];
#pragma unroll
        for (int nt = 0; nt < 8; nt++)
#pragma unroll
            for (int e = 0; e < 4; e++) s[nt][e] = 0.f;
#pragma unroll
        for (int kk = 0; kk < 8; kk++) {
            float af[4];
            int r = w * 16 + g;
            af[0] = qs[r    ][kk * 8 + t4];
            af[1] = qs[r + 8][kk * 8 + t4];
            af[2] = qs[r    ][kk * 8 + t4 + 4];
            af[3] = qs[r + 8][kk * 8 + t4 + 4];
#pragma unroll
            for (int nt = 0; nt < 8; nt++) {
                float bf[2];
                bf[0] = ks[nt * 8 + g][kk * 8 + t4];
                bf[1] = ks[nt * 8 + g][kk * 8 + t4 + 4];
                mma8(s[nt], af, bf);
            }
        }

        if (jt == qt) {
            const int r0 = w * 16 + g;
#pragma unroll
            for (int nt = 0; nt < 8; nt++) {
                int c0 = nt * 8 + 2 * t4;
                if (c0     > r0    ) s[nt][0] = -1e30f;
                if (c0 + 1 > r0    ) s[nt][1] = -1e30f;
                if (c0     > r0 + 8) s[nt][2] = -1e30f;
                if (c0 + 1 > r0 + 8) s[nt][3] = -1e30f;
            }
        }

        float mx0 = -INFINITY, mx1 = -INFINITY;
#pragma unroll
        for (int nt = 0; nt < 8; nt++) {
            mx0 = fmaxf(mx0, fmaxf(s[nt][0], s[nt][1]));
            mx1 = fmaxf(mx1, fmaxf(s[nt][2], s[nt][3]));
        }
        mx0 = red_max4(mx0);
        mx1 = red_max4(mx1);
        const float mn0 = fmaxf(m0, mx0), mn1 = fmaxf(m1, mx1);
        const float a0 = __expf(m0 - mn0), a1 = __expf(m1 - mn1);

        float rs0 = 0.f, rs1 = 0.f;
#pragma unroll
        for (int nt = 0; nt < 8; nt++) {
            s[nt][0] = __expf(s[nt][0] - mn0);
            s[nt][1] = __expf(s[nt][1] - mn0);
            s[nt][2] = __expf(s[nt][2] - mn1);
            s[nt][3] = __expf(s[nt][3] - mn1);
            rs0 += s[nt][0] + s[nt][1];
            rs1 += s[nt][2] + s[nt][3];
        }
        rs0 = red_sum4(rs0);
        rs1 = red_sum4(rs1);
        l0 = l0 * a0 + rs0;
        l1 = l1 * a1 + rs1;
#pragma unroll
        for (int nt = 0; nt < 8; nt++) {
            o[nt][0] *= a0; o[nt][1] *= a0;
            o[nt][2] *= a1; o[nt][3] *= a1;
        }
        m0 = mn0; m1 = mn1;

        // P scratch: written and read by the SAME warp's 16-row band
        {
            const int r0 = w * 16 + g;
#pragma unroll
            for (int nt = 0; nt < 8; nt++) {
                int c0 = nt * 8 + 2 * t4;
                ps[r0    ][c0]     = to_tf32(s[nt][0]);
                ps[r0    ][c0 + 1] = to_tf32(s[nt][1]);
                ps[r0 + 8][c0]     = to_tf32(s[nt][2]);
                ps[r0 + 8][c0 + 1] = to_tf32(s[nt][3]);
            }
        }
        __syncwarp();

#pragma unroll
        for (int kk = 0; kk < 8; kk++) {
            float af[4];
            int r = w * 16 + g;
            af[0] = ps[r    ][kk * 8 + t4];
            af[1] = ps[r + 8][kk * 8 + t4];
            af[2] = ps[r    ][kk * 8 + t4 + 4];
            af[3] = ps[r + 8][kk * 8 + t4 + 4];
#pragma unroll
            for (int nt = 0; nt < 8; nt++) {
                float bf[2];
                bf[0] = vs[nt * 8 + g][kk * 8 + t4];
                bf[1] = vs[nt * 8 + g][kk * 8 + t4 + 4];
                mma8(o[nt], af, bf);
            }
        }
        __syncthreads();
    }

    // normalize, tf32-round (feeds proj GEMM), write [t][h*64+d]
    const float il0 = 1.f / l0, il1 = 1.f / l1;
    const int tr0 = qt * 64 + w * 16 + g;
#pragma unroll
    for (int nt = 0; nt < 8; nt++) {
        int col = h * 64 + nt * 8 + 2 * t4;
        *(float2*)(g_ob + tr0 * DMODEL + col) =
            make_float2(to_tf32(o[nt][0] * il0), to_tf32(o[nt][1] * il0));
        *(float2*)(g_ob + (tr0 + 8) * DMODEL + col) =
            make_float2(to_tf32(o[nt][2] * il1), to_tf32(o[nt][3] * il1));
    }
}

// ---------------------------------------------------------------------------
// Launch
// ---------------------------------------------------------------------------
extern "C" void kernel_launch(void* const* d_in, const int* in_sizes, int n_in,
                              void* d_out, int out_size)
{
    (void)in_sizes; (void)n_in; (void)out_size;
    const float* x    = (const float*)d_in[0];
    const float* vi   = (const float*)d_in[1];
    const float* Wq   = (const float*)d_in[2];
    const float* Wk   = (const float*)d_in[3];
    const float* Wv   = (const float*)d_in[4];
    const float* Wp   = (const float*)d_in[5];
    const float* lamb = (const float*)d_in[6];

    cudaFuncSetAttribute(gemm_qkv_k,
                         cudaFuncAttributeMaxDynamicSharedMemorySize, QKV_SMEM);
    cudaFuncSetAttribute(gemm_proj_k,
                         cudaFuncAttributeMaxDynamicSharedMemorySize, PROJ_SMEM);

    round_kernel<<<3840, 256>>>(x, Wq, Wk, Wv, Wp);
    gemm_qkv_k<<<dim3(16, 18), 256, QKV_SMEM>>>();
    epilogue_kernel<<<dim3(12, 64), 256>>>(vi, lamb);

    const int attn_smem = 4 * 64 * 68 * (int)sizeof(float);  // 69632 B
    cudaFuncSetAttribute(attn_kernel, cudaFuncAttributeMaxDynamicSharedMemorySize,
                         attn_smem);
    attn_kernel<<<dim3(32, 12), 128, attn_smem>>>();

    gemm_proj_k<<<dim3(16, 12), 256, PROJ_SMEM>>>((float*)d_out);
}